// round 2
// baseline (speedup 1.0000x reference)
#include <cuda_runtime.h>
#include <cstdint>

// Problem shape (fixed for this dataset):
//   pool: f32  [16, 128, 128, 64]  -> 16,777,216 elements
//   ind : i32  same shape (JAX x64-disabled downcasts int64 -> int32),
//              values in [0, 4,194,304)
//   out : f32  [16, 256, 256, 64]  -> 67,108,864 elements
// Per-batch flat scatter-ADD (duplicates sum).

static constexpr int  IN_TOTAL      = 16 * 128 * 128 * 64;   // 16,777,216
static constexpr int  IN_TOTAL_V4   = IN_TOTAL / 4;          // 4,194,304
static constexpr int  PB_IN_V4_LOG2 = 18;                    // per-batch input elems/4 = 2^18
static constexpr int  OUT_FLAT_LOG2 = 22;                    // 4,194,304 = 2^22
static constexpr long OUT_TOTAL     = 67108864;

// ---------------------------------------------------------------------------
// Kernel 1: zero the output (vectorized float4 stores, streaming)
// ---------------------------------------------------------------------------
__global__ void zero_out_kernel(float4* __restrict__ out4, int n4) {
    int i = blockIdx.x * blockDim.x + threadIdx.x;
    if (i < n4) {
        out4[i] = make_float4(0.f, 0.f, 0.f, 0.f);
    }
}

// ---------------------------------------------------------------------------
// Kernel 2: scatter-add. Each thread handles 4 consecutive input elements:
//   - 1x float4 load (pool), 1x int4 load (indices) — front-batched for MLP
//   - 4x atomicAdd (no return -> REDG) into out[b*OUT_FLAT + idx]
// ---------------------------------------------------------------------------
__global__ void unpool_scatter_kernel(const float4* __restrict__ pool4,
                                      const int4*   __restrict__ ind4,
                                      float*        __restrict__ out,
                                      int n4) {
    int t = blockIdx.x * blockDim.x + threadIdx.x;
    if (t >= n4) return;

    // Front-batch all loads (independent -> MLP)
    float4 p = pool4[t];
    int4   i = ind4[t];

    int  b    = t >> PB_IN_V4_LOG2;                 // batch index
    long base = (long)b << OUT_FLAT_LOG2;           // b * out_flat

    atomicAdd(out + base + (long)(unsigned)i.x, p.x);
    atomicAdd(out + base + (long)(unsigned)i.y, p.y);
    atomicAdd(out + base + (long)(unsigned)i.z, p.z);
    atomicAdd(out + base + (long)(unsigned)i.w, p.w);
}

// ---------------------------------------------------------------------------
extern "C" void kernel_launch(void* const* d_in, const int* in_sizes, int n_in,
                              void* d_out, int out_size) {
    const float4* pool4 = (const float4*)d_in[0];
    const int4*   ind4  = (const int4*)d_in[1];
    float*        out   = (float*)d_out;

    // Zero output: 67,108,864 floats = 16,777,216 float4
    {
        int n4 = (int)(OUT_TOTAL / 4);
        int threads = 256;
        int blocks  = (n4 + threads - 1) / threads;
        zero_out_kernel<<<blocks, threads>>>((float4*)out, n4);
    }

    // Scatter-add
    {
        int n4 = IN_TOTAL_V4;
        int threads = 256;
        int blocks  = (n4 + threads - 1) / threads;
        unpool_scatter_kernel<<<blocks, threads>>>(pool4, ind4, out, n4);
    }
}

// round 3
// speedup vs baseline: 1.3955x; 1.3955x over previous
#include <cuda_runtime.h>
#include <cstdint>

// Problem shape (fixed for this dataset):
//   pool: f32  [16, 128, 128, 64]  -> 16,777,216 elements
//   ind : i32  same shape, values in [0, 4,194,304)
//   out : f32  [16, 256, 256, 64]  -> 67,108,864 elements (256 MB)
// Per-batch flat scatter-ADD (duplicates sum).
//
// Strategy: chunked zero+scatter so each output chunk stays L2-resident
// between its memset and its atomics. 4 chunks x 4 batches:
//   chunk out slice = 4 * 16 MB = 64 MB  (< 126 MB L2)
//   chunk inputs    = 16 MB pool + 16 MB ind (streamed)
// DRAM traffic: 128 MB input + 256 MB final writeback (vs ~836 MB unchunked).

static constexpr int  IN_TOTAL       = 16 * 128 * 128 * 64;  // 16,777,216
static constexpr int  PB_IN_V4_LOG2  = 18;                   // per-batch input elems/4
static constexpr int  OUT_FLAT_LOG2  = 22;                   // per-batch output elems = 2^22
static constexpr int  BATCHES        = 16;
static constexpr int  BATCHES_PER_CHUNK = 4;
static constexpr int  NCHUNKS        = BATCHES / BATCHES_PER_CHUNK;

static constexpr int  CHUNK_IN_V4    = BATCHES_PER_CHUNK << PB_IN_V4_LOG2;   // 1,048,576
static constexpr long CHUNK_OUT_ELEM = (long)BATCHES_PER_CHUNK << OUT_FLAT_LOG2; // 16,777,216

// ---------------------------------------------------------------------------
// Scatter-add for one chunk of BATCHES_PER_CHUNK batches.
// Each thread handles 4 consecutive input elements:
//   1x float4 load (pool) + 1x int4 load (indices), then 4x atomicAdd (REDG).
// out points at the start of this chunk's output slice.
// ---------------------------------------------------------------------------
__global__ void unpool_scatter_chunk(const float4* __restrict__ pool4,
                                     const int4*   __restrict__ ind4,
                                     float*        __restrict__ out,
                                     int n4) {
    int t = blockIdx.x * blockDim.x + threadIdx.x;
    if (t >= n4) return;

    // Front-batch loads (independent -> MLP)
    float4 p = pool4[t];
    int4   i = ind4[t];

    int  b    = t >> PB_IN_V4_LOG2;          // batch within chunk (0..3)
    long base = (long)b << OUT_FLAT_LOG2;    // local batch output base

    atomicAdd(out + base + (long)(unsigned)i.x, p.x);
    atomicAdd(out + base + (long)(unsigned)i.y, p.y);
    atomicAdd(out + base + (long)(unsigned)i.z, p.z);
    atomicAdd(out + base + (long)(unsigned)i.w, p.w);
}

// ---------------------------------------------------------------------------
extern "C" void kernel_launch(void* const* d_in, const int* in_sizes, int n_in,
                              void* d_out, int out_size) {
    const float4* pool4 = (const float4*)d_in[0];
    const int4*   ind4  = (const int4*)d_in[1];
    float*        out   = (float*)d_out;

    const int threads = 256;
    const int blocks  = (CHUNK_IN_V4 + threads - 1) / threads;

    for (int c = 0; c < NCHUNKS; ++c) {
        float* out_chunk = out + (long)c * CHUNK_OUT_ELEM;

        // Zero this chunk's output slice (stays L2-resident for the scatter).
        cudaMemsetAsync(out_chunk, 0, CHUNK_OUT_ELEM * sizeof(float), 0);

        // Scatter-add this chunk's 4 batches while the slice is hot in L2.
        unpool_scatter_chunk<<<blocks, threads>>>(
            pool4 + (long)c * CHUNK_IN_V4,
            ind4  + (long)c * CHUNK_IN_V4,
            out_chunk,
            CHUNK_IN_V4);
    }
}